// round 2
// baseline (speedup 1.0000x reference)
#include <cuda_runtime.h>
#include <stdint.h>

#define N_POINTS 1200000
#define NFEAT 5
#define GXD 400
#define GYD 400
#define NCELLS (GXD*GYD)          // 160000
#define MAXV 60000
#define MAXP 32
#define OUT_COORD_OFF (MAXV*MAXP*NFEAT)        // 9,600,000
#define OUT_NUM_OFF   (OUT_COORD_OFF + MAXV*3) // 9,780,000
#define NSCB 625                   // 160000 / 256

__device__ int g_cellcount[NCELLS];
__device__ int g_cellcursor[NCELLS];
__device__ int g_cellstart[NCELLS];
__device__ int g_cellvox[NCELLS];
__device__ int g_ptcell[N_POINTS];
__device__ int g_bucket[N_POINTS];
__device__ int g_bsumA[NSCB];
__device__ int g_bsumB[NSCB];
__device__ int g_totvox;

// ---------------- init: zero per-cell counters ----------------
__global__ void k_init() {
    int i = blockIdx.x * blockDim.x + threadIdx.x;
    if (i < NCELLS) { g_cellcount[i] = 0; g_cellcursor[i] = 0; }
}

// ---------------- assign: point -> cell, count ----------------
__global__ void k_assign(const float* __restrict__ pts) {
    int i = blockIdx.x * blockDim.x + threadIdx.x;
    if (i >= N_POINTS) return;
    const float* p = pts + (size_t)i * NFEAT;
    float x = p[0], y = p[1], z = p[2];
    // exact: (v - (-50))/0.25 == (v+50)*4 ; (v - (-5))/8 == (v+5)*0.125
    int cx = (int)floorf((x + 50.0f) * 4.0f);
    int cy = (int)floorf((y + 50.0f) * 4.0f);
    int cz = (int)floorf((z + 5.0f) * 0.125f);
    int cell = -1;
    if (cx >= 0 && cx < GXD && cy >= 0 && cy < GYD && cz == 0) {
        cell = cy * GXD + cx;
        atomicAdd(&g_cellcount[cell], 1);
    }
    g_ptcell[i] = cell;
}

// ---------------- scanA: per-block sums ----------------
__global__ void k_scanA() {
    int c = blockIdx.x * 256 + threadIdx.x;
    int cnt = g_cellcount[c];
    int occ = cnt > 0 ? 1 : 0;
    #pragma unroll
    for (int o = 16; o; o >>= 1) {
        cnt += __shfl_down_sync(0xffffffffu, cnt, o);
        occ += __shfl_down_sync(0xffffffffu, occ, o);
    }
    __shared__ int wa[8], wb[8];
    int w = threadIdx.x >> 5, l = threadIdx.x & 31;
    if (l == 0) { wa[w] = cnt; wb[w] = occ; }
    __syncthreads();
    if (threadIdx.x == 0) {
        int sa = 0, sb = 0;
        #pragma unroll
        for (int j = 0; j < 8; j++) { sa += wa[j]; sb += wb[j]; }
        g_bsumA[blockIdx.x] = sa; g_bsumB[blockIdx.x] = sb;
    }
}

// ---------------- scanB: scan the 625 block sums (exclusive, in place) ----------------
__global__ void k_scanB() {
    __shared__ int sa[1024], sb[1024];
    int t = threadIdx.x;
    int a = (t < NSCB) ? g_bsumA[t] : 0;
    int b = (t < NSCB) ? g_bsumB[t] : 0;
    sa[t] = a; sb[t] = b;
    __syncthreads();
    for (int off = 1; off < 1024; off <<= 1) {
        int va = (t >= off) ? sa[t - off] : 0;
        int vb = (t >= off) ? sb[t - off] : 0;
        __syncthreads();
        sa[t] += va; sb[t] += vb;
        __syncthreads();
    }
    if (t < NSCB) { g_bsumA[t] = sa[t] - a; g_bsumB[t] = sb[t] - b; }
    if (t == NSCB - 1) g_totvox = sb[t];   // total occupied cells
}

// ---------------- scanC: final per-cell exclusive prefixes ----------------
__global__ void k_scanC() {
    int t = threadIdx.x;
    int c = blockIdx.x * 256 + t;
    int cnt = g_cellcount[c];
    int occ = cnt > 0 ? 1 : 0;
    __shared__ int sa[256], sb[256];
    sa[t] = cnt; sb[t] = occ;
    __syncthreads();
    for (int off = 1; off < 256; off <<= 1) {
        int va = (t >= off) ? sa[t - off] : 0;
        int vb = (t >= off) ? sb[t - off] : 0;
        __syncthreads();
        sa[t] += va; sb[t] += vb;
        __syncthreads();
    }
    g_cellstart[c] = sa[t] - cnt + g_bsumA[blockIdx.x];
    g_cellvox[c]   = sb[t] - occ + g_bsumB[blockIdx.x];
}

// ---------------- scatter: point index into per-cell bucket ----------------
__global__ void k_scatter() {
    int i = blockIdx.x * blockDim.x + threadIdx.x;
    if (i >= N_POINTS) return;
    int c = g_ptcell[i];
    if (c < 0) return;
    int pos = g_cellstart[c] + atomicAdd(&g_cellcursor[c], 1);
    g_bucket[pos] = i;
}

// ---------------- emit: one warp per cell, stable order via index sort ----------------
__global__ void k_emit(const float* __restrict__ pts, float* __restrict__ out) {
    int gw   = (blockIdx.x * blockDim.x + threadIdx.x) >> 5;
    int lane = threadIdx.x & 31;
    int w    = threadIdx.x >> 5;
    __shared__ float4 sbuf4[8][40];   // 640 B staging per warp
    __shared__ int    sidx[8][32];
    if (gw >= NCELLS) return;
    int cell = gw;
    int cnt = g_cellcount[cell];
    if (cnt == 0) return;
    int v = g_cellvox[cell];
    if (v >= MAXV) return;
    int st = g_cellstart[cell];
    float* sb = (float*)sbuf4[w];
    int n;
    if (cnt <= 32) {
        n = cnt;
        int pidx = (lane < cnt) ? g_bucket[st + lane] : 0x7fffffff;
        int rank = 0;
        #pragma unroll
        for (int k = 0; k < 32; k++) {
            int o = __shfl_sync(0xffffffffu, pidx, k);
            rank += (o < pidx) ? 1 : 0;
        }
        if (lane < cnt) sidx[w][rank] = pidx;
    } else {
        n = 32;
        if (lane == 0) {  // rare path: keep 32 smallest original indices in order
            int keep[32]; int m = 0;
            for (int j = 0; j < cnt; j++) {
                int pi = g_bucket[st + j];
                if (m < 32) {
                    int p = m++;
                    while (p > 0 && keep[p-1] > pi) { keep[p] = keep[p-1]; p--; }
                    keep[p] = pi;
                } else if (pi < keep[31]) {
                    int p = 31;
                    while (p > 0 && keep[p-1] > pi) { keep[p] = keep[p-1]; p--; }
                    keep[p] = pi;
                }
            }
            for (int r = 0; r < 32; r++) sidx[w][r] = keep[r];
        }
    }
    // zero staging then gather kept points
    #pragma unroll
    for (int j = lane; j < 160; j += 32) sb[j] = 0.0f;
    __syncwarp();
    if (lane < n) {
        int idx = sidx[w][lane];
        const float* p = pts + (size_t)idx * NFEAT;
        #pragma unroll
        for (int f = 0; f < NFEAT; f++) sb[lane * NFEAT + f] = p[f];
    }
    __syncwarp();
    // coalesced 640B write per voxel
    float4* dst = (float4*)(out + (size_t)v * (MAXP * NFEAT));
    #pragma unroll
    for (int j = lane; j < 40; j += 32) dst[j] = sbuf4[w][j];
    if (lane == 0) {
        int cy = cell / GXD, cx = cell - cy * GXD;
        float* oc = out + OUT_COORD_OFF + (size_t)v * 3;
        oc[0] = 0.0f;           // z
        oc[1] = (float)cy;      // y
        oc[2] = (float)cx;      // x
        out[OUT_NUM_OFF + v] = (float)n;
    }
}

// ---------------- tail: zero voxels beyond occupied count (no-op here) ----------------
__global__ void k_tail(float* __restrict__ out) {
    int gw   = (blockIdx.x * blockDim.x + threadIdx.x) >> 5;
    int lane = threadIdx.x & 31;
    if (gw >= MAXV) return;
    if (gw < g_totvox) return;
    float4 z = make_float4(0.f, 0.f, 0.f, 0.f);
    float4* dst = (float4*)(out + (size_t)gw * (MAXP * NFEAT));
    for (int j = lane; j < 40; j += 32) dst[j] = z;
    if (lane == 0) {
        float* oc = out + OUT_COORD_OFF + (size_t)gw * 3;
        oc[0] = 0.f; oc[1] = 0.f; oc[2] = 0.f;
        out[OUT_NUM_OFF + gw] = 0.f;
    }
}

extern "C" void kernel_launch(void* const* d_in, const int* in_sizes, int n_in,
                              void* d_out, int out_size) {
    const float* pts = (const float*)d_in[0];
    float* out = (float*)d_out;
    (void)in_sizes; (void)n_in; (void)out_size;

    k_init   <<<NSCB, 256>>>();
    k_assign <<<(N_POINTS + 255) / 256, 256>>>(pts);
    k_scanA  <<<NSCB, 256>>>();
    k_scanB  <<<1, 1024>>>();
    k_scanC  <<<NSCB, 256>>>();
    k_scatter<<<(N_POINTS + 255) / 256, 256>>>();
    k_emit   <<<(NCELLS * 32 + 255) / 256, 256>>>(pts, out);
    k_tail   <<<(MAXV * 32 + 255) / 256, 256>>>(out);
}